// round 16
// baseline (speedup 1.0000x reference)
#include <cuda_runtime.h>
#include <cuda_bf16.h>
#include <cuda_fp16.h>
#include <math.h>
#include <stdint.h>

// Problem constants
#define HIDDEN   4096
#define NHEADS   32
#define NKV      8
#define HDIM     128
#define QSIZE    (NHEADS * HDIM)          // 4096
#define KVSIZE   (NKV * HDIM)             // 1024
#define QKV_N    (QSIZE + 2 * KVSIZE)     // 6144
#define BATCH    2
#define SEQ      2048
#define MROWS    4096
#define SCALE_F  0.08838834764831845f     // 128^-0.5
#define ROPE_THETA 10000.0

// ---------------------------------------------------------------------------
// Scratch (allocation-free rule: __device__ globals) — bf16 split operands only
// ---------------------------------------------------------------------------
__device__ __align__(16) __nv_bfloat16 g_hid_hi [(size_t)MROWS * HIDDEN];
__device__ __align__(16) __nv_bfloat16 g_hid_lo [(size_t)MROWS * HIDDEN];
__device__ __align__(16) __nv_bfloat16 g_qkv_hi [(size_t)MROWS * QKV_N];
__device__ __align__(16) __nv_bfloat16 g_qkv_lo [(size_t)MROWS * QKV_N];
__device__ __align__(16) __nv_bfloat16 g_attn_hi[(size_t)MROWS * QSIZE];
__device__ __align__(16) __nv_bfloat16 g_attn_lo[(size_t)MROWS * QSIZE];
__device__ __align__(16) __nv_bfloat16 g_wqkvT_hi[(size_t)QKV_N * HIDDEN];  // [N][K]
__device__ __align__(16) __nv_bfloat16 g_wqkvT_lo[(size_t)QKV_N * HIDDEN];
__device__ __align__(16) __nv_bfloat16 g_woT_hi  [(size_t)HIDDEN * QSIZE];  // [N][K]
__device__ __align__(16) __nv_bfloat16 g_woT_lo  [(size_t)HIDDEN * QSIZE];
// flags: [0] dtype (0=f32,1=bf16,2=f16), [1] c0-is-hidden, [2] positions-int64
__device__ int   g_flags[3];

// ---------------------------------------------------------------------------
// PTX helpers (plain sm_10x — no arch-specific features)
// ---------------------------------------------------------------------------
__device__ __forceinline__ uint32_t smem_u32(const void* p) {
    uint32_t a;
    asm("{ .reg .u64 t; cvta.to.shared.u64 t, %1; cvt.u32.u64 %0, t; }"
        : "=r"(a) : "l"(p));
    return a;
}
__device__ __forceinline__ void cp16(uint32_t dst, const void* src) {
    asm volatile("cp.async.cg.shared.global [%0], [%1], 16;"
                 :: "r"(dst), "l"(src));
}
__device__ __forceinline__ void ldm4(uint32_t* r, uint32_t a) {
    asm volatile("ldmatrix.sync.aligned.m8n8.x4.shared.b16 {%0,%1,%2,%3}, [%4];"
                 : "=r"(r[0]), "=r"(r[1]), "=r"(r[2]), "=r"(r[3]) : "r"(a));
}
__device__ __forceinline__ void ldm4t(uint32_t* r, uint32_t a) {
    asm volatile("ldmatrix.sync.aligned.m8n8.x4.trans.shared.b16 {%0,%1,%2,%3}, [%4];"
                 : "=r"(r[0]), "=r"(r[1]), "=r"(r[2]), "=r"(r[3]) : "r"(a));
}
__device__ __forceinline__ void mma_bf16(float* c, const uint32_t* a,
                                         const uint32_t* b) {
    asm volatile(
        "mma.sync.aligned.m16n8k16.row.col.f32.bf16.bf16.f32 "
        "{%0,%1,%2,%3}, {%4,%5,%6,%7}, {%8,%9}, {%0,%1,%2,%3};"
        : "+f"(c[0]), "+f"(c[1]), "+f"(c[2]), "+f"(c[3])
        : "r"(a[0]), "r"(a[1]), "r"(a[2]), "r"(a[3]), "r"(b[0]), "r"(b[1]));
}
// dtype-dispatched scalar load (dt per g_flags[0])
__device__ __forceinline__ float ld_any(const void* s, size_t idx, int dt) {
    if (dt == 1) return __bfloat162float(((const __nv_bfloat16*)s)[idx]);
    if (dt == 2) return __half2float(((const __half*)s)[idx]);
    return ((const float*)s)[idx];
}

// ---------------------------------------------------------------------------
// Sniffer (verified).
// ---------------------------------------------------------------------------
__global__ void sniff_kernel(const uint32_t* __restrict__ wq_words,
                             const void* __restrict__ c0,
                             const uint32_t* __restrict__ pos_words) {
    int lo = 0, hi = 0;
    for (int i = 0; i < 128; i++) {
        uint32_t w = wq_words[(size_t)i * 997 + 1];
        int el = (w >> 7)  & 0xFF;
        int eh = (w >> 23) & 0xFF;
        if (el >= 90 && el <= 140) lo++;
        if (eh >= 90 && eh <= 140) hi++;
    }
    int dt;
    if (lo > 64 && hi > 64)      dt = 1;
    else if (hi > 64)            dt = 0;
    else                         dt = 2;
    g_flags[0] = dt;

    float s = 0.f;
    for (int i = 0; i < 256; i++) {
        size_t idx = (size_t)i * 65536;
        float v;
        if (dt == 1)      v = __bfloat162float(((const __nv_bfloat16*)c0)[idx]);
        else if (dt == 2) v = __half2float(((const __half*)c0)[idx]);
        else              v = ((const float*)c0)[idx];
        s += fabsf(v);
    }
    g_flags[1] = (s > 25.6f) ? 1 : 0;

    g_flags[2] = (pos_words[1] == 1u && pos_words[3] == 3u) ? 0 : 1;
}

// ---------------------------------------------------------------------------
// Fused convert + split (verified).
// ---------------------------------------------------------------------------
__global__ void csplit_kernel(const void* __restrict__ ps,
                              const void* __restrict__ pn,
                              __nv_bfloat16* __restrict__ hi,
                              __nv_bfloat16* __restrict__ lo, size_t n) {
    const void* src = g_flags[1] ? ps : pn;
    size_t i = ((size_t)blockIdx.x * blockDim.x + threadIdx.x) * 4;
    if (i >= n) return;
    int dt = g_flags[0];
    #pragma unroll
    for (int j = 0; j < 4; j++) {
        float v = ld_any(src, i + j, dt);
        __nv_bfloat16 h = __float2bfloat16(v);
        hi[i + j] = h;
        lo[i + j] = __float2bfloat16(v - __bfloat162float(h));
    }
}

// ---------------------------------------------------------------------------
// Fused transpose + convert + split (verified).
// ---------------------------------------------------------------------------
__global__ void tsplit_raw(const void* __restrict__ ps,
                           const void* __restrict__ pn,
                           __nv_bfloat16* __restrict__ hiT,
                           __nv_bfloat16* __restrict__ loT,
                           int R, int C, int use_sel) {
    __shared__ float t[32][33];
    const void* src = use_sel ? (g_flags[1] ? ps : pn) : ps;
    int dt = g_flags[0];
    int bx = blockIdx.x * 32;
    int by = blockIdx.y * 32;
    int tx = threadIdx.x, ty = threadIdx.y;
    #pragma unroll
    for (int i = ty; i < 32; i += 8)
        t[i][tx] = ld_any(src, (size_t)(by + i) * C + bx + tx, dt);
    __syncthreads();
    #pragma unroll
    for (int i = ty; i < 32; i += 8) {
        float v = t[tx][i];
        __nv_bfloat16 h = __float2bfloat16(v);
        size_t o = (size_t)(bx + i) * R + by + tx;
        hiT[o] = h;
        loT[o] = __float2bfloat16(v - __bfloat162float(h));
    }
}

// ---------------------------------------------------------------------------
// Split-bf16 HMMA GEMM. CTA tile 64x128, BK=32, double-buffered, 60KB smem
// -> 3 CTAs/SM (24 warps). Warp layout 2m x 4n (warp tile 32x32, 8 acc frags
// per term pass). mode 1: dtype-matched store. mode 2: fused RoPE + split.
// ---------------------------------------------------------------------------
#define GM_RSTRIDE 80u
#define GM_ATILE   5120u      // 64 rows * 80 B
#define GM_BTILE   10240u     // 128 rows * 80 B
#define GM_STAGE   30720u     // Ah|Al|Bh|Bl
#define GM_SMEM    (2 * GM_STAGE)   // 61440 B

__global__ __launch_bounds__(256, 3)
void gemm_mma(const __nv_bfloat16* __restrict__ Ahi,
              const __nv_bfloat16* __restrict__ Alo,
              const __nv_bfloat16* __restrict__ Bhi,
              const __nv_bfloat16* __restrict__ Blo,
              void* __restrict__ Cv, int M, int N, int K, int mode,
              const int* __restrict__ positions,
              __nv_bfloat16* __restrict__ outH,
              __nv_bfloat16* __restrict__ outL) {
    extern __shared__ char smraw[];
    const uint32_t sb = smem_u32(smraw);
    const int tid    = threadIdx.x;
    const int wid    = tid >> 5;
    const int lane   = tid & 31;
    const int warp_m = wid >> 2;     // 0..1 -> 32-row half
    const int warp_n = wid & 3;      // 0..3 -> 32-col quarter
    const int tm = blockIdx.y * 64;
    const int tn = blockIdx.x * 128;

    const char* gA[2] = { (const char*)(Ahi + (size_t)tm * K),
                          (const char*)(Alo + (size_t)tm * K) };
    const char* gB[2] = { (const char*)(Bhi + (size_t)tn * K),
                          (const char*)(Blo + (size_t)tn * K) };
    const size_t rowb = (size_t)K * 2;

    float c[2][4][4];
    #pragma unroll
    for (int mf = 0; mf < 2; mf++)
        #pragma unroll
        for (int nf = 0; nf < 4; nf++)
            #pragma unroll
            for (int q = 0; q < 4; q++) c[mf][nf][q] = 0.f;

    const uint32_t a_off = (uint32_t)(lane & 15) * GM_RSTRIDE
                         + (uint32_t)(lane >> 4) * 16u;
    const uint32_t b_off = (uint32_t)((lane & 7) + ((lane >> 4) << 3)) * GM_RSTRIDE
                         + (uint32_t)((lane >> 3) & 1) * 16u;

    auto load_stage = [&](int ck, int buf) {
        uint32_t base = sb + (uint32_t)buf * GM_STAGE;
        size_t coff = (size_t)ck * 64;          // 32 bf16 = 64 bytes
        // A tiles: 512 cp16 (2 mats x 64 rows x 4 chunks); it = 0,1
        #pragma unroll
        for (int it = 0; it < 2; it++) {
            int i   = tid + it * 256;           // 0..511
            int m   = i >> 8;                   // 0 Ah, 1 Al
            int idx = i & 255;
            int r   = idx >> 2;
            int s   = idx & 3;
            cp16(base + (uint32_t)m * GM_ATILE + (uint32_t)r * GM_RSTRIDE
                      + (uint32_t)s * 16u,
                 gA[m] + (size_t)r * rowb + coff + (size_t)s * 16);
        }
        // B tiles: 1024 cp16 (2 mats x 128 rows x 4 chunks); it = 0..3
        #pragma unroll
        for (int it = 0; it < 4; it++) {
            int i   = tid + it * 256;           // 0..1023
            int m   = i >> 9;                   // 0 Bh, 1 Bl
            int idx = i & 511;
            int r   = idx >> 2;
            int s   = idx & 3;
            cp16(base + 2u * GM_ATILE + (uint32_t)m * GM_BTILE
                      + (uint32_t)r * GM_RSTRIDE + (uint32_t)s * 16u,
                 gB[m] + (size_t)r * rowb + coff + (size_t)s * 16);
        }
        asm volatile("cp.async.commit_group;" ::: "memory");
    };

    const int NC = K / 32;
    load_stage(0, 0);

    for (int ck = 0; ck < NC; ck++) {
        int b = ck & 1;
        if (ck + 1 < NC) {
            load_stage(ck + 1, b ^ 1);
            asm volatile("cp.async.wait_group 1;" ::: "memory");
        } else {
            asm volatile("cp.async.wait_group 0;" ::: "memory");
        }
        __syncthreads();

        const uint32_t st = sb + (uint32_t)b * GM_STAGE;
        const uint32_t ah_base = st + (uint32_t)(warp_m * 32) * GM_RSTRIDE;
        const uint32_t al_base = ah_base + GM_ATILE;
        const uint32_t bh_base = st + 2u * GM_ATILE
                               + (uint32_t)(warp_n * 32) * GM_RSTRIDE;
        const uint32_t bl_base = bh_base + GM_BTILE;

        #pragma unroll
        for (int ks = 0; ks < 2; ks++) {
            const uint32_t kb = (uint32_t)ks * 32u;
            uint32_t ah[2][4], al[2][4], bh[4][2], bl[4][2];
            #pragma unroll
            for (int mf = 0; mf < 2; mf++) {
                ldm4(ah[mf], ah_base + a_off + (uint32_t)mf * (16u * GM_RSTRIDE) + kb);
                ldm4(al[mf], al_base + a_off + (uint32_t)mf * (16u * GM_RSTRIDE) + kb);
            }
            #pragma unroll
            for (int p = 0; p < 2; p++) {
                uint32_t r4[4];
                ldm4(r4, bh_base + b_off + (uint32_t)p * (16u * GM_RSTRIDE) + kb);
                bh[2 * p][0] = r4[0]; bh[2 * p][1] = r4[1];
                bh[2 * p + 1][0] = r4[2]; bh[2 * p + 1][1] = r4[3];
                ldm4(r4, bl_base + b_off + (uint32_t)p * (16u * GM_RSTRIDE) + kb);
                bl[2 * p][0] = r4[0]; bl[2 * p][1] = r4[1];
                bl[2 * p + 1][0] = r4[2]; bl[2 * p + 1][1] = r4[3];
            }
            // term-outer: 8 independent accumulators per pass
            #pragma unroll
            for (int mf = 0; mf < 2; mf++)
                #pragma unroll
                for (int nf = 0; nf < 4; nf++)
                    mma_bf16(c[mf][nf], ah[mf], bh[nf]);
            #pragma unroll
            for (int mf = 0; mf < 2; mf++)
                #pragma unroll
                for (int nf = 0; nf < 4; nf++)
                    mma_bf16(c[mf][nf], ah[mf], bl[nf]);
            #pragma unroll
            for (int mf = 0; mf < 2; mf++)
                #pragma unroll
                for (int nf = 0; nf < 4; nf++)
                    mma_bf16(c[mf][nf], al[mf], bh[nf]);
        }
        __syncthreads();
    }

    const int g  = lane >> 2;
    const int tg = lane & 3;

    if (mode == 2) {
        // --- fused RoPE + split epilogue (no fp64 division) ---
        float* T = (float*)smraw;     // [64][132] fp32 tile = 33792 B <= 61440
        #pragma unroll
        for (int mf = 0; mf < 2; mf++)
            #pragma unroll
            for (int nf = 0; nf < 4; nf++) {
                int r0 = warp_m * 32 + mf * 16 + g;
                int cc = warp_n * 32 + nf * 8 + tg * 2;
                T[r0 * 132 + cc]           = c[mf][nf][0];
                T[r0 * 132 + cc + 1]       = c[mf][nf][1];
                T[(r0 + 8) * 132 + cc]     = c[mf][nf][2];
                T[(r0 + 8) * 132 + cc + 1] = c[mf][nf][3];
            }
        __syncthreads();

        const int jcol  = tid & 63;
        const int rbase = tid >> 6;           // 0..3
        const bool do_rope = (tn < QSIZE + KVSIZE);   // Q or K head
        const double TWO_PI = 6.283185307179586476925286766559;
        double invf01 = 0.0;                  // inv_freq / (2*pi)
        if (do_rope)
            invf01 = exp(-(double)jcol * (log(ROPE_THETA) / 64.0)) / TWO_PI;

        #pragma unroll 4
        for (int k = 0; k < 16; k++) {
            int r = rbase + k * 4;
            int row_g = tm + r;
            float x1 = T[r * 132 + jcol];
            float x2 = T[r * 132 + jcol + 64];
            float y1 = x1, y2 = x2;
            if (do_rope) {
                int pv = g_flags[2] ? positions[2 * row_g] : positions[row_g];
                double f01 = (double)pv * invf01;          // angle / (2*pi)
                double frac = f01 - floor(f01);            // no division
                float cc, ss;
                sincosf((float)(frac * TWO_PI), &cc, &ss);
                y1 = x1 * cc + x2 * ss;      // verified NEGATED rotation
                y2 = x2 * cc - x1 * ss;
            }
            size_t o = (size_t)row_g * QKV_N + tn + jcol;
            __nv_bfloat16 h1 = __float2bfloat16(y1);
            __nv_bfloat16 h2 = __float2bfloat16(y2);
            outH[o]      = h1;
            outL[o]      = __float2bfloat16(y1 - __bfloat162float(h1));
            outH[o + 64] = h2;
            outL[o + 64] = __float2bfloat16(y2 - __bfloat162float(h2));
        }
        return;
    }

    // --- mode 1: dtype-matched store ---
    const int dt = g_flags[0];
    #pragma unroll
    for (int mf = 0; mf < 2; mf++) {
        #pragma unroll
        for (int nf = 0; nf < 4; nf++) {
            int row0 = tm + warp_m * 32 + mf * 16 + g;
            int col  = tn + warp_n * 32 + nf * 8 + tg * 2;
            float c0 = c[mf][nf][0], c1 = c[mf][nf][1];
            float c2 = c[mf][nf][2], c3 = c[mf][nf][3];
            if (dt == 1) {
                __nv_bfloat16* C = (__nv_bfloat16*)Cv;
                __nv_bfloat162 p0(__float2bfloat16(c0), __float2bfloat16(c1));
                __nv_bfloat162 p1(__float2bfloat16(c2), __float2bfloat16(c3));
                *(__nv_bfloat162*)&C[(size_t)row0 * N + col]       = p0;
                *(__nv_bfloat162*)&C[(size_t)(row0 + 8) * N + col] = p1;
            } else if (dt == 2) {
                __half* C = (__half*)Cv;
                __half2 p0(__float2half(c0), __float2half(c1));
                __half2 p1(__float2half(c2), __float2half(c3));
                *(__half2*)&C[(size_t)row0 * N + col]       = p0;
                *(__half2*)&C[(size_t)(row0 + 8) * N + col] = p1;
            } else {
                float* C = (float*)Cv;
                *(float2*)&C[(size_t)row0 * N + col]       = make_float2(c0, c1);
                *(float2*)&C[(size_t)(row0 + 8) * N + col] = make_float2(c2, c3);
            }
        }
    }
}

// ---------------------------------------------------------------------------
// Flash attention on HMMA (verified, unchanged from Round 15).
// ---------------------------------------------------------------------------
#define FRS 272u
#define PRS 144u
#define FA_QH   0u
#define FA_QL   17408u
#define FA_KV   34816u
#define FA_SS   174080u
#define FA_PH   190720u
#define FA_PL   199936u
#define FA_ROWS 209152u
#define FA_TOTAL 209920u

__global__ __launch_bounds__(256, 1)
void flash_mma(const __nv_bfloat16* __restrict__ qh,
               const __nv_bfloat16* __restrict__ ql,
               __nv_bfloat16* __restrict__ outH,
               __nv_bfloat16* __restrict__ outL) {
    extern __shared__ char smraw[];
    const uint32_t sb = smem_u32(smraw);
    float* Ss   = (float*)(smraw + FA_SS);
    float* mrow = (float*)(smraw + FA_ROWS);
    float* lrow = mrow + 64;
    float* arow = lrow + 64;

    const int qt  = blockIdx.x;
    const int h   = blockIdx.y;
    const int b   = blockIdx.z;
    const int tid = threadIdx.x;
    const int wid  = tid >> 5;
    const int lane = tid & 31;
    const int warp_m = wid >> 1;
    const int warp_n = wid & 1;
    const int g  = lane >> 2;
    const int tg = lane & 3;
    const int kvh = h >> 2;

    const size_t seqbase = (size_t)b * SEQ;
    const size_t qoff = (seqbase + (size_t)qt * 64) * QKV_N + (size_t)h * HDIM;
    const size_t koff = seqbase * QKV_N + QSIZE + (size_t)kvh * HDIM;
    const size_t voff = koff + KVSIZE;

    #pragma unroll
    for (int it = 0; it < 8; it++) {
        int i = tid + it * 256;
        int m = i >> 10;
        int idx = i & 1023;
        int r = idx >> 4, s = idx & 15;
        const char* src = (const char*)((m ? ql : qh) + qoff + (size_t)r * QKV_N)
                        + s * 16;
        cp16(sb + (m ? FA_QL : FA_QH) + (uint32_t)r * FRS + (uint32_t)s * 16u, src);
    }
    if (tid < 64) { mrow[tid] = -INFINITY; lrow[tid] = 0.f; }

    auto load_kv = [&](int kt, int st) {
        uint32_t base = sb + FA_KV + (uint32_t)st * 69632u;
        size_t rb = (seqbase + (size_t)kt * 64) * QKV_N;
        #pragma unroll
        for (int it = 0; it < 16; it++) {
            int i = tid + it * 256;
            int m = i >> 10;
            int idx = i & 1023;
            int r = idx >> 4, s = idx & 15;
            const __nv_bfloat16* gp = (m & 1) ? ql : qh;
            size_t go = rb + (size_t)r * QKV_N + (m >= 2 ? voff - seqbase * QKV_N
                                                         : koff - seqbase * QKV_N);
            cp16(base + (uint32_t)m * 17408u + (uint32_t)r * FRS + (uint32_t)s * 16u,
                 (const char*)(gp + go) + s * 16);
        }
        asm volatile("cp.async.commit_group;" ::: "memory");
    };

    load_kv(0, 0);
    asm volatile("cp.async.commit_group;" ::: "memory");

    float of[8][4];
    #pragma unroll
    for (int nf = 0; nf < 8; nf++)
        #pragma unroll
        for (int q = 0; q < 4; q++) of[nf][q] = 0.f;

    const uint32_t a_off = (uint32_t)(lane & 15) * FRS + (uint32_t)(lane >> 4) * 16u;
    const uint32_t b_off = (uint32_t)((lane & 7) + ((lane >> 4) << 3)) * FRS
                         + (uint32_t)((lane >> 3) & 1) * 16u;
    const uint32_t ap_off = (uint32_t)(lane & 15) * PRS + (uint32_t)(lane >> 4) * 16u;
    const uint32_t v_off = (uint32_t)((lane & 7) + ((lane >> 3) & 1) * 8) * FRS
                         + (uint32_t)(lane >> 4) * 16u;

    for (int kt = 0; kt <= qt; kt++) {
        int st = kt & 1;
        if (kt + 1 <= qt) {
            load_kv(kt + 1, st ^ 1);
            asm volatile("cp.async.wait_group 1;" ::: "memory");
        } else {
            asm volatile("cp.async.wait_group 0;" ::: "memory");
        }
        __syncthreads();

        const uint32_t kvbase = sb + FA_KV + (uint32_t)st * 69632u;

        float sc[4][4];
        #pragma unroll
        for (int nf = 0; nf < 4; nf++)
            #pragma unroll
            for (int q = 0; q < 4; q++) sc[nf][q] = 0.f;

        const uint32_t qh_b = sb + FA_QH + (uint32_t)(warp_m * 16) * FRS;
        const uint32_t ql_b = sb + FA_QL + (uint32_t)(warp_m * 16) * FRS;
        const uint32_t kh_b = kvbase + (uint32_t)(warp_n * 32) * FRS;
        const uint32_t kl_b = kvbase + 17408u + (uint32_t)(warp_n * 32) * FRS;

        #pragma unroll
        for (int ks = 0; ks < 8; ks++) {
            const uint32_t kb = (uint32_t)ks * 32u;
            uint32_t aH[4], aL[4], bH[4][2], bL[4][2];
            ldm4(aH, qh_b + a_off + kb);
            ldm4(aL, ql_b + a_off + kb);
            #pragma unroll
            for (int p = 0; p < 2; p++) {
                uint32_t r4[4];
                ldm4(r4, kh_b + b_off + (uint32_t)p * (16u * FRS) + kb);
                bH[2 * p][0] = r4[0]; bH[2 * p][1] = r4[1];
                bH[2 * p + 1][0] = r4[2]; bH[2 * p + 1][1] = r4[3];
                ldm4(r4, kl_b + b_off + (uint32_t)p * (16u * FRS) + kb);
                bL[2 * p][0] = r4[0]; bL[2 * p][1] = r4[1];
                bL[2 * p + 1][0] = r4[2]; bL[2 * p + 1][1] = r4[3];
            }
            #pragma unroll
            for (int nf = 0; nf < 4; nf++) mma_bf16(sc[nf], aH, bH[nf]);
            #pragma unroll
            for (int nf = 0; nf < 4; nf++) mma_bf16(sc[nf], aH, bL[nf]);
            #pragma unroll
            for (int nf = 0; nf < 4; nf++) mma_bf16(sc[nf], aL, bH[nf]);
        }

        {
            int r0 = warp_m * 16 + g;
            int qg0 = qt * 64 + r0;
            #pragma unroll
            for (int nf = 0; nf < 4; nf++) {
                int col = warp_n * 32 + nf * 8 + tg * 2;
                int kg  = kt * 64 + col;
                Ss[r0 * 65 + col]           = (kg     <= qg0)     ? sc[nf][0] * SCALE_F : -1e30f;
                Ss[r0 * 65 + col + 1]       = (kg + 1 <= qg0)     ? sc[nf][1] * SCALE_F : -1e30f;
                Ss[(r0 + 8) * 65 + col]     = (kg     <= qg0 + 8) ? sc[nf][2] * SCALE_F : -1e30f;
                Ss[(r0 + 8) * 65 + col + 1] = (kg + 1 <= qg0 + 8) ? sc[nf][3] * SCALE_F : -1e30f;
            }
        }
        __syncthreads();

        {
            int r  = tid >> 2;
            int q4 = (tid & 3) * 16;
            float mold = mrow[r];
            float mx = mold;
            #pragma unroll
            for (int cc = 0; cc < 16; cc++)
                mx = fmaxf(mx, Ss[r * 65 + q4 + cc]);
            mx = fmaxf(mx, __shfl_xor_sync(0xffffffffu, mx, 1));
            mx = fmaxf(mx, __shfl_xor_sync(0xffffffffu, mx, 2));
            float sum = 0.f;
            __nv_bfloat16* Ph = (__nv_bfloat16*)(smraw + FA_PH);
            __nv_bfloat16* Pl = (__nv_bfloat16*)(smraw + FA_PL);
            #pragma unroll
            for (int cc = 0; cc < 16; cc++) {
                float p = __expf(Ss[r * 65 + q4 + cc] - mx);
                sum += p;
                __nv_bfloat16 hi = __float2bfloat16(p);
                Ph[r * 72 + q4 + cc] = hi;
                Pl[r * 72 + q4 + cc] = __float2bfloat16(p - __bfloat162float(hi));
            }
            sum += __shfl_xor_sync(0xffffffffu, sum, 1);
            sum += __shfl_xor_sync(0xffffffffu, sum, 2);
            if ((tid & 3) == 0) {
                float al = __expf(mold - mx);
                lrow[r] = lrow[r] * al + sum;
                mrow[r] = mx;
                arow[r] = al;
            }
        }
        __syncthreads();

        {
            float al0 = arow[warp_m * 16 + g];
            float al1 = arow[warp_m * 16 + g + 8];
            #pragma unroll
            for (int nf = 0; nf < 8; nf++) {
                of[nf][0] *= al0; of[nf][1] *= al0;
                of[nf][2] *= al1; of[nf][3] *= al1;
            }
        }
        {
            const uint32_t ph_b = sb + FA_PH + (uint32_t)(warp_m * 16) * PRS;
            const uint32_t pl_b = sb + FA_PL + (uint32_t)(warp_m * 16) * PRS;
            const uint32_t vh_b = kvbase + 2u * 17408u + (uint32_t)(warp_n * 64) * 2u;
            const uint32_t vl_b = vh_b + 17408u;
            #pragma unroll
            for (int ks = 0; ks < 4; ks++) {
                uint32_t pH[4], pL[4], vH[8][2], vL[8][2];
                ldm4(pH, ph_b + ap_off + (uint32_t)ks * 32u);
                ldm4(pL, pl_b + ap_off + (uint32_t)ks * 32u);
                #pragma unroll
                for (int cl = 0; cl < 4; cl++) {
                    uint32_t r4[4];
                    ldm4t(r4, vh_b + v_off + (uint32_t)(ks * 16) * FRS
                              + (uint32_t)cl * 32u);
                    vH[2 * cl][0] = r4[0]; vH[2 * cl][1] = r4[1];
                    vH[2 * cl + 1][0] = r4[2]; vH[2 * cl + 1][1] = r4[3];
                    ldm4t(r4, vl_b + v_off + (uint32_t)(ks * 16) * FRS
                              + (uint32_t)cl * 32u);
                    vL[2 * cl][0] = r4[0]; vL[2 * cl][1] = r4[1];
                    vL[2 * cl + 1][0] = r4[2]; vL[2 * cl + 1][1] = r4[3];
                }
                #pragma unroll
                for (int nf = 0; nf < 8; nf++) mma_bf16(of[nf], pH, vH[nf]);
                #pragma unroll
                for (int nf = 0; nf < 8; nf++) mma_bf16(of[nf], pH, vL[nf]);
                #pragma unroll
                for (int nf = 0; nf < 8; nf++) mma_bf16(of[nf], pL, vH[nf]);
            }
        }
        __syncthreads();
    }

    {
        float inv0 = 1.0f / lrow[warp_m * 16 + g];
        float inv1 = 1.0f / lrow[warp_m * 16 + g + 8];
        size_t row0 = (seqbase + (size_t)qt * 64 + warp_m * 16 + g) * QSIZE
                    + (size_t)h * HDIM;
        size_t row1 = row0 + 8 * QSIZE;
        #pragma unroll
        for (int nf = 0; nf < 8; nf++) {
            int d = warp_n * 64 + nf * 8 + tg * 2;
            float v0 = of[nf][0] * inv0, v1 = of[nf][1] * inv0;
            float v2 = of[nf][2] * inv1, v3 = of[nf][3] * inv1;
            __nv_bfloat16 h0 = __float2bfloat16(v0), h1 = __float2bfloat16(v1);
            __nv_bfloat16 h2 = __float2bfloat16(v2), h3 = __float2bfloat16(v3);
            *(__nv_bfloat162*)&outH[row0 + d] = __nv_bfloat162(h0, h1);
            *(__nv_bfloat162*)&outH[row1 + d] = __nv_bfloat162(h2, h3);
            *(__nv_bfloat162*)&outL[row0 + d] = __nv_bfloat162(
                __float2bfloat16(v0 - __bfloat162float(h0)),
                __float2bfloat16(v1 - __bfloat162float(h1)));
            *(__nv_bfloat162*)&outL[row1 + d] = __nv_bfloat162(
                __float2bfloat16(v2 - __bfloat162float(h2)),
                __float2bfloat16(v3 - __bfloat162float(h3)));
        }
    }
}

// ---------------------------------------------------------------------------
// Launch
// ---------------------------------------------------------------------------
extern "C" void kernel_launch(void* const* d_in, const int* in_sizes, int n_in,
                              void* d_out, int out_size) {
    const void* positions = nullptr;
    const void* W_qkv_raw = nullptr;
    const void* c16[2]    = {nullptr, nullptr};
    int n16 = 0;
    for (int i = 0; i < n_in; i++) {
        if (in_sizes[i] == MROWS)               positions = d_in[i];
        else if (in_sizes[i] == HIDDEN * QKV_N) W_qkv_raw = d_in[i];
        else if (in_sizes[i] == MROWS * HIDDEN && n16 < 2)
            c16[n16++] = d_in[i];
    }
    const void* c0 = c16[0];
    const void* c1 = c16[1];

    __nv_bfloat16 *hidH, *hidL, *qkvH, *qkvL, *attnH, *attnL;
    __nv_bfloat16 *wqTH, *wqTL, *woTH, *woTL;
    cudaGetSymbolAddress((void**)&hidH,  g_hid_hi);
    cudaGetSymbolAddress((void**)&hidL,  g_hid_lo);
    cudaGetSymbolAddress((void**)&qkvH,  g_qkv_hi);
    cudaGetSymbolAddress((void**)&qkvL,  g_qkv_lo);
    cudaGetSymbolAddress((void**)&attnH, g_attn_hi);
    cudaGetSymbolAddress((void**)&attnL, g_attn_lo);
    cudaGetSymbolAddress((void**)&wqTH,  g_wqkvT_hi);
    cudaGetSymbolAddress((void**)&wqTL,  g_wqkvT_lo);
    cudaGetSymbolAddress((void**)&woTH,  g_woT_hi);
    cudaGetSymbolAddress((void**)&woTL,  g_woT_lo);

    // 0) Sniff dtype / hidden-vs-W_o / positions width
    sniff_kernel<<<1, 1>>>((const uint32_t*)W_qkv_raw, c0,
                           (const uint32_t*)positions);

    // 0b) Fused convert+split for hidden; transpose+convert+split for weights
    {
        size_t nh = (size_t)MROWS * HIDDEN;
        int thr = 256;
        csplit_kernel<<<(int)((nh / 4 + thr - 1) / thr), thr>>>(c0, c1,
                                                                hidH, hidL, nh);
        dim3 blk(32, 8);
        tsplit_raw<<<dim3(QKV_N / 32, HIDDEN / 32), blk>>>(
            W_qkv_raw, W_qkv_raw, wqTH, wqTL, HIDDEN, QKV_N, 0);
        tsplit_raw<<<dim3(HIDDEN / 32, QSIZE / 32), blk>>>(
            c1, c0, woTH, woTL, QSIZE, HIDDEN, 1);
    }

    cudaFuncSetAttribute(gemm_mma, cudaFuncAttributeMaxDynamicSharedMemorySize,
                         GM_SMEM);
    cudaFuncSetAttribute(flash_mma, cudaFuncAttributeMaxDynamicSharedMemorySize,
                         FA_TOTAL);

    // 1) QKV projection + fused RoPE + split output (mode 2)
    {
        dim3 grid(QKV_N / 128, MROWS / 64);
        gemm_mma<<<grid, 256, GM_SMEM>>>(hidH, hidL, wqTH, wqTL,
                                         nullptr, MROWS, QKV_N, HIDDEN, 2,
                                         (const int*)positions, qkvH, qkvL);
    }

    // 2) Flash attention on HMMA (writes split output directly)
    {
        dim3 grid(SEQ / 64, NHEADS, BATCH);
        flash_mma<<<grid, 256, FA_TOTAL>>>(qkvH, qkvL, attnH, attnL);
    }

    // 3) Output projection (mode 1: dtype-matched store)
    {
        dim3 grid(HIDDEN / 128, MROWS / 64);
        gemm_mma<<<grid, 256, GM_SMEM>>>(attnH, attnL, woTH, woTL,
                                         d_out, MROWS, HIDDEN, QSIZE, 1,
                                         nullptr, nullptr, nullptr);
    }
}

// round 17
// speedup vs baseline: 1.0480x; 1.0480x over previous
#include <cuda_runtime.h>
#include <cuda_bf16.h>
#include <cuda_fp16.h>
#include <math.h>
#include <stdint.h>

// Problem constants
#define HIDDEN   4096
#define NHEADS   32
#define NKV      8
#define HDIM     128
#define QSIZE    (NHEADS * HDIM)          // 4096
#define KVSIZE   (NKV * HDIM)             // 1024
#define QKV_N    (QSIZE + 2 * KVSIZE)     // 6144
#define BATCH    2
#define SEQ      2048
#define MROWS    4096
#define SCALE_F  0.08838834764831845f     // 128^-0.5
#define ROPE_THETA 10000.0

// ---------------------------------------------------------------------------
// Scratch (allocation-free rule: __device__ globals) — bf16 split operands only
// ---------------------------------------------------------------------------
__device__ __align__(16) __nv_bfloat16 g_hid_hi [(size_t)MROWS * HIDDEN];
__device__ __align__(16) __nv_bfloat16 g_hid_lo [(size_t)MROWS * HIDDEN];
__device__ __align__(16) __nv_bfloat16 g_qkv_hi [(size_t)MROWS * QKV_N];
__device__ __align__(16) __nv_bfloat16 g_qkv_lo [(size_t)MROWS * QKV_N];
__device__ __align__(16) __nv_bfloat16 g_attn_hi[(size_t)MROWS * QSIZE];
__device__ __align__(16) __nv_bfloat16 g_attn_lo[(size_t)MROWS * QSIZE];
__device__ __align__(16) __nv_bfloat16 g_wqkvT_hi[(size_t)QKV_N * HIDDEN];  // [N][K]
__device__ __align__(16) __nv_bfloat16 g_wqkvT_lo[(size_t)QKV_N * HIDDEN];
__device__ __align__(16) __nv_bfloat16 g_woT_hi  [(size_t)HIDDEN * QSIZE];  // [N][K]
__device__ __align__(16) __nv_bfloat16 g_woT_lo  [(size_t)HIDDEN * QSIZE];
// flags: [0] dtype (0=f32,1=bf16,2=f16), [1] c0-is-hidden, [2] positions-int64
__device__ int   g_flags[3];

// ---------------------------------------------------------------------------
// PTX helpers (plain sm_10x — no arch-specific features)
// ---------------------------------------------------------------------------
__device__ __forceinline__ uint32_t smem_u32(const void* p) {
    uint32_t a;
    asm("{ .reg .u64 t; cvta.to.shared.u64 t, %1; cvt.u32.u64 %0, t; }"
        : "=r"(a) : "l"(p));
    return a;
}
__device__ __forceinline__ void cp16(uint32_t dst, const void* src) {
    asm volatile("cp.async.cg.shared.global [%0], [%1], 16;"
                 :: "r"(dst), "l"(src));
}
__device__ __forceinline__ void ldm4(uint32_t* r, uint32_t a) {
    asm volatile("ldmatrix.sync.aligned.m8n8.x4.shared.b16 {%0,%1,%2,%3}, [%4];"
                 : "=r"(r[0]), "=r"(r[1]), "=r"(r[2]), "=r"(r[3]) : "r"(a));
}
__device__ __forceinline__ void ldm4t(uint32_t* r, uint32_t a) {
    asm volatile("ldmatrix.sync.aligned.m8n8.x4.trans.shared.b16 {%0,%1,%2,%3}, [%4];"
                 : "=r"(r[0]), "=r"(r[1]), "=r"(r[2]), "=r"(r[3]) : "r"(a));
}
__device__ __forceinline__ void mma_bf16(float* c, const uint32_t* a,
                                         const uint32_t* b) {
    asm volatile(
        "mma.sync.aligned.m16n8k16.row.col.f32.bf16.bf16.f32 "
        "{%0,%1,%2,%3}, {%4,%5,%6,%7}, {%8,%9}, {%0,%1,%2,%3};"
        : "+f"(c[0]), "+f"(c[1]), "+f"(c[2]), "+f"(c[3])
        : "r"(a[0]), "r"(a[1]), "r"(a[2]), "r"(a[3]), "r"(b[0]), "r"(b[1]));
}
// dtype-dispatched scalar load (dt per g_flags[0])
__device__ __forceinline__ float ld_any(const void* s, size_t idx, int dt) {
    if (dt == 1) return __bfloat162float(((const __nv_bfloat16*)s)[idx]);
    if (dt == 2) return __half2float(((const __half*)s)[idx]);
    return ((const float*)s)[idx];
}

// ---------------------------------------------------------------------------
// Sniffer (verified).
// ---------------------------------------------------------------------------
__global__ void sniff_kernel(const uint32_t* __restrict__ wq_words,
                             const void* __restrict__ c0,
                             const uint32_t* __restrict__ pos_words) {
    int lo = 0, hi = 0;
    for (int i = 0; i < 128; i++) {
        uint32_t w = wq_words[(size_t)i * 997 + 1];
        int el = (w >> 7)  & 0xFF;
        int eh = (w >> 23) & 0xFF;
        if (el >= 90 && el <= 140) lo++;
        if (eh >= 90 && eh <= 140) hi++;
    }
    int dt;
    if (lo > 64 && hi > 64)      dt = 1;
    else if (hi > 64)            dt = 0;
    else                         dt = 2;
    g_flags[0] = dt;

    float s = 0.f;
    for (int i = 0; i < 256; i++) {
        size_t idx = (size_t)i * 65536;
        float v;
        if (dt == 1)      v = __bfloat162float(((const __nv_bfloat16*)c0)[idx]);
        else if (dt == 2) v = __half2float(((const __half*)c0)[idx]);
        else              v = ((const float*)c0)[idx];
        s += fabsf(v);
    }
    g_flags[1] = (s > 25.6f) ? 1 : 0;

    g_flags[2] = (pos_words[1] == 1u && pos_words[3] == 3u) ? 0 : 1;
}

// ---------------------------------------------------------------------------
// Fused convert + split (verified).
// ---------------------------------------------------------------------------
__global__ void csplit_kernel(const void* __restrict__ ps,
                              const void* __restrict__ pn,
                              __nv_bfloat16* __restrict__ hi,
                              __nv_bfloat16* __restrict__ lo, size_t n) {
    const void* src = g_flags[1] ? ps : pn;
    size_t i = ((size_t)blockIdx.x * blockDim.x + threadIdx.x) * 4;
    if (i >= n) return;
    int dt = g_flags[0];
    #pragma unroll
    for (int j = 0; j < 4; j++) {
        float v = ld_any(src, i + j, dt);
        __nv_bfloat16 h = __float2bfloat16(v);
        hi[i + j] = h;
        lo[i + j] = __float2bfloat16(v - __bfloat162float(h));
    }
}

// ---------------------------------------------------------------------------
// Fused transpose + convert + split (verified).
// ---------------------------------------------------------------------------
__global__ void tsplit_raw(const void* __restrict__ ps,
                           const void* __restrict__ pn,
                           __nv_bfloat16* __restrict__ hiT,
                           __nv_bfloat16* __restrict__ loT,
                           int R, int C, int use_sel) {
    __shared__ float t[32][33];
    const void* src = use_sel ? (g_flags[1] ? ps : pn) : ps;
    int dt = g_flags[0];
    int bx = blockIdx.x * 32;
    int by = blockIdx.y * 32;
    int tx = threadIdx.x, ty = threadIdx.y;
    #pragma unroll
    for (int i = ty; i < 32; i += 8)
        t[i][tx] = ld_any(src, (size_t)(by + i) * C + bx + tx, dt);
    __syncthreads();
    #pragma unroll
    for (int i = ty; i < 32; i += 8) {
        float v = t[tx][i];
        __nv_bfloat16 h = __float2bfloat16(v);
        size_t o = (size_t)(bx + i) * R + by + tx;
        hiT[o] = h;
        loT[o] = __float2bfloat16(v - __bfloat162float(h));
    }
}

// ---------------------------------------------------------------------------
// Split-bf16 HMMA GEMM. CTA tile 128x128 (Round-15 proven shape), BK=32,
// double-buffered, 80KB smem, occ 2. SINGLE barrier per K-chunk: the top
// barrier simultaneously guarantees (a) chunk ck's data visible to all
// warps and (b) all warps done reading buffer b^1, so the prefetch of
// chunk ck+1 into b^1 right after it is hazard-free and overlaps the MMA.
// ---------------------------------------------------------------------------
#define GM_RSTRIDE 80u
#define GM_TILE    10240u     // 128 rows * 80 B
#define GM_STAGE   40960u     // 4 tiles
#define GM_SMEM    (2 * GM_STAGE)   // 81920 B

__global__ __launch_bounds__(256, 2)
void gemm_mma(const __nv_bfloat16* __restrict__ Ahi,
              const __nv_bfloat16* __restrict__ Alo,
              const __nv_bfloat16* __restrict__ Bhi,
              const __nv_bfloat16* __restrict__ Blo,
              void* __restrict__ Cv, int M, int N, int K, int mode,
              const int* __restrict__ positions,
              __nv_bfloat16* __restrict__ outH,
              __nv_bfloat16* __restrict__ outL) {
    extern __shared__ char smraw[];
    const uint32_t sb = smem_u32(smraw);
    const int tid    = threadIdx.x;
    const int wid    = tid >> 5;
    const int lane   = tid & 31;
    const int warp_m = wid >> 2;
    const int warp_n = wid & 3;
    const int tm = blockIdx.y * 128;
    const int tn = blockIdx.x * 128;

    const char* gsrc[4] = {
        (const char*)(Ahi + (size_t)tm * K),
        (const char*)(Alo + (size_t)tm * K),
        (const char*)(Bhi + (size_t)tn * K),
        (const char*)(Blo + (size_t)tn * K)
    };
    const size_t rowb = (size_t)K * 2;

    float c[4][4][4];
    #pragma unroll
    for (int mf = 0; mf < 4; mf++)
        #pragma unroll
        for (int nf = 0; nf < 4; nf++)
            #pragma unroll
            for (int q = 0; q < 4; q++) c[mf][nf][q] = 0.f;

    const uint32_t a_off = (uint32_t)(lane & 15) * GM_RSTRIDE
                         + (uint32_t)(lane >> 4) * 16u;
    const uint32_t b_off = (uint32_t)((lane & 7) + ((lane >> 4) << 3)) * GM_RSTRIDE
                         + (uint32_t)((lane >> 3) & 1) * 16u;

    auto load_stage = [&](int ck, int buf) {
        uint32_t base = sb + (uint32_t)buf * GM_STAGE;
        size_t coff = (size_t)ck * 64;          // 32 bf16 = 64 bytes
        #pragma unroll
        for (int it = 0; it < 8; it++) {
            int i   = tid + it * 256;           // 0..2047
            int m   = i >> 9;
            int idx = i & 511;
            int r   = idx >> 2;
            int s   = idx & 3;
            cp16(base + (uint32_t)m * GM_TILE + (uint32_t)r * GM_RSTRIDE
                      + (uint32_t)s * 16u,
                 gsrc[m] + (size_t)r * rowb + coff + (size_t)s * 16);
        }
        asm volatile("cp.async.commit_group;" ::: "memory");
    };

    const int NC = K / 32;
    load_stage(0, 0);

    for (int ck = 0; ck < NC; ck++) {
        int b = ck & 1;
        // Single barrier per chunk: my chunk-ck cp.asyncs landed, then the
        // CTA-wide barrier makes them visible AND certifies every warp has
        // finished reading buffer b^1 (its MMA of chunk ck-1 is complete).
        asm volatile("cp.async.wait_group 0;" ::: "memory");
        __syncthreads();
        if (ck + 1 < NC) load_stage(ck + 1, b ^ 1);   // overlaps MMA below

        const uint32_t st = sb + (uint32_t)b * GM_STAGE;
        const uint32_t ah_base = st + (uint32_t)(warp_m * 64) * GM_RSTRIDE;
        const uint32_t al_base = ah_base + GM_TILE;
        const uint32_t bh_base = st + 2u * GM_TILE
                               + (uint32_t)(warp_n * 32) * GM_RSTRIDE;
        const uint32_t bl_base = bh_base + GM_TILE;

        #pragma unroll
        for (int ks = 0; ks < 2; ks++) {
            const uint32_t kb = (uint32_t)ks * 32u;
            uint32_t ah[4][4], al[4][4], bh[4][2], bl[4][2];
            #pragma unroll
            for (int mf = 0; mf < 4; mf++) {
                ldm4(ah[mf], ah_base + a_off + (uint32_t)mf * (16u * GM_RSTRIDE) + kb);
                ldm4(al[mf], al_base + a_off + (uint32_t)mf * (16u * GM_RSTRIDE) + kb);
            }
            #pragma unroll
            for (int p = 0; p < 2; p++) {
                uint32_t r4[4];
                ldm4(r4, bh_base + b_off + (uint32_t)p * (16u * GM_RSTRIDE) + kb);
                bh[2 * p][0] = r4[0]; bh[2 * p][1] = r4[1];
                bh[2 * p + 1][0] = r4[2]; bh[2 * p + 1][1] = r4[3];
                ldm4(r4, bl_base + b_off + (uint32_t)p * (16u * GM_RSTRIDE) + kb);
                bl[2 * p][0] = r4[0]; bl[2 * p][1] = r4[1];
                bl[2 * p + 1][0] = r4[2]; bl[2 * p + 1][1] = r4[3];
            }
            // term-outer: 16 independent accumulators per pass
            #pragma unroll
            for (int mf = 0; mf < 4; mf++)
                #pragma unroll
                for (int nf = 0; nf < 4; nf++)
                    mma_bf16(c[mf][nf], ah[mf], bh[nf]);
            #pragma unroll
            for (int mf = 0; mf < 4; mf++)
                #pragma unroll
                for (int nf = 0; nf < 4; nf++)
                    mma_bf16(c[mf][nf], ah[mf], bl[nf]);
            #pragma unroll
            for (int mf = 0; mf < 4; mf++)
                #pragma unroll
                for (int nf = 0; nf < 4; nf++)
                    mma_bf16(c[mf][nf], al[mf], bh[nf]);
        }
    }

    const int g  = lane >> 2;
    const int tg = lane & 3;

    if (mode == 2) {
        // --- fused RoPE + split epilogue (no fp64 division) ---
        __syncthreads();              // all warps done with ldmatrix reads
        float* T = (float*)smraw;     // [128][132] fp32 tile = 67584 B <= 81920
        #pragma unroll
        for (int mf = 0; mf < 4; mf++)
            #pragma unroll
            for (int nf = 0; nf < 4; nf++) {
                int r0 = warp_m * 64 + mf * 16 + g;
                int cc = warp_n * 32 + nf * 8 + tg * 2;
                T[r0 * 132 + cc]           = c[mf][nf][0];
                T[r0 * 132 + cc + 1]       = c[mf][nf][1];
                T[(r0 + 8) * 132 + cc]     = c[mf][nf][2];
                T[(r0 + 8) * 132 + cc + 1] = c[mf][nf][3];
            }
        __syncthreads();

        const int jcol  = tid & 63;
        const int rbase = tid >> 6;           // 0..3
        const bool do_rope = (tn < QSIZE + KVSIZE);   // Q or K head
        const double TWO_PI = 6.283185307179586476925286766559;
        double invf01 = 0.0;                  // inv_freq / (2*pi)
        if (do_rope)
            invf01 = exp(-(double)jcol * (log(ROPE_THETA) / 64.0)) / TWO_PI;

        #pragma unroll 4
        for (int k = 0; k < 32; k++) {
            int r = rbase + k * 4;
            int row_g = tm + r;
            float x1 = T[r * 132 + jcol];
            float x2 = T[r * 132 + jcol + 64];
            float y1 = x1, y2 = x2;
            if (do_rope) {
                int pv = g_flags[2] ? positions[2 * row_g] : positions[row_g];
                double f01 = (double)pv * invf01;          // angle / (2*pi)
                double frac = f01 - floor(f01);            // no division
                float cc, ss;
                sincosf((float)(frac * TWO_PI), &cc, &ss);
                y1 = x1 * cc + x2 * ss;      // verified NEGATED rotation
                y2 = x2 * cc - x1 * ss;
            }
            size_t o = (size_t)row_g * QKV_N + tn + jcol;
            __nv_bfloat16 h1 = __float2bfloat16(y1);
            __nv_bfloat16 h2 = __float2bfloat16(y2);
            outH[o]      = h1;
            outL[o]      = __float2bfloat16(y1 - __bfloat162float(h1));
            outH[o + 64] = h2;
            outL[o + 64] = __float2bfloat16(y2 - __bfloat162float(h2));
        }
        return;
    }

    // --- mode 1: dtype-matched store ---
    const int dt = g_flags[0];
    #pragma unroll
    for (int mf = 0; mf < 4; mf++) {
        #pragma unroll
        for (int nf = 0; nf < 4; nf++) {
            int row0 = tm + warp_m * 64 + mf * 16 + g;
            int col  = tn + warp_n * 32 + nf * 8 + tg * 2;
            float c0 = c[mf][nf][0], c1 = c[mf][nf][1];
            float c2 = c[mf][nf][2], c3 = c[mf][nf][3];
            if (dt == 1) {
                __nv_bfloat16* C = (__nv_bfloat16*)Cv;
                __nv_bfloat162 p0(__float2bfloat16(c0), __float2bfloat16(c1));
                __nv_bfloat162 p1(__float2bfloat16(c2), __float2bfloat16(c3));
                *(__nv_bfloat162*)&C[(size_t)row0 * N + col]       = p0;
                *(__nv_bfloat162*)&C[(size_t)(row0 + 8) * N + col] = p1;
            } else if (dt == 2) {
                __half* C = (__half*)Cv;
                __half2 p0(__float2half(c0), __float2half(c1));
                __half2 p1(__float2half(c2), __float2half(c3));
                *(__half2*)&C[(size_t)row0 * N + col]       = p0;
                *(__half2*)&C[(size_t)(row0 + 8) * N + col] = p1;
            } else {
                float* C = (float*)Cv;
                *(float2*)&C[(size_t)row0 * N + col]       = make_float2(c0, c1);
                *(float2*)&C[(size_t)(row0 + 8) * N + col] = make_float2(c2, c3);
            }
        }
    }
}

// ---------------------------------------------------------------------------
// Flash attention on HMMA (verified, unchanged from Round 15).
// ---------------------------------------------------------------------------
#define FRS 272u
#define PRS 144u
#define FA_QH   0u
#define FA_QL   17408u
#define FA_KV   34816u
#define FA_SS   174080u
#define FA_PH   190720u
#define FA_PL   199936u
#define FA_ROWS 209152u
#define FA_TOTAL 209920u

__global__ __launch_bounds__(256, 1)
void flash_mma(const __nv_bfloat16* __restrict__ qh,
               const __nv_bfloat16* __restrict__ ql,
               __nv_bfloat16* __restrict__ outH,
               __nv_bfloat16* __restrict__ outL) {
    extern __shared__ char smraw[];
    const uint32_t sb = smem_u32(smraw);
    float* Ss   = (float*)(smraw + FA_SS);
    float* mrow = (float*)(smraw + FA_ROWS);
    float* lrow = mrow + 64;
    float* arow = lrow + 64;

    const int qt  = blockIdx.x;
    const int h   = blockIdx.y;
    const int b   = blockIdx.z;
    const int tid = threadIdx.x;
    const int wid  = tid >> 5;
    const int lane = tid & 31;
    const int warp_m = wid >> 1;
    const int warp_n = wid & 1;
    const int g  = lane >> 2;
    const int tg = lane & 3;
    const int kvh = h >> 2;

    const size_t seqbase = (size_t)b * SEQ;
    const size_t qoff = (seqbase + (size_t)qt * 64) * QKV_N + (size_t)h * HDIM;
    const size_t koff = seqbase * QKV_N + QSIZE + (size_t)kvh * HDIM;
    const size_t voff = koff + KVSIZE;

    #pragma unroll
    for (int it = 0; it < 8; it++) {
        int i = tid + it * 256;
        int m = i >> 10;
        int idx = i & 1023;
        int r = idx >> 4, s = idx & 15;
        const char* src = (const char*)((m ? ql : qh) + qoff + (size_t)r * QKV_N)
                        + s * 16;
        cp16(sb + (m ? FA_QL : FA_QH) + (uint32_t)r * FRS + (uint32_t)s * 16u, src);
    }
    if (tid < 64) { mrow[tid] = -INFINITY; lrow[tid] = 0.f; }

    auto load_kv = [&](int kt, int st) {
        uint32_t base = sb + FA_KV + (uint32_t)st * 69632u;
        size_t rb = (seqbase + (size_t)kt * 64) * QKV_N;
        #pragma unroll
        for (int it = 0; it < 16; it++) {
            int i = tid + it * 256;
            int m = i >> 10;
            int idx = i & 1023;
            int r = idx >> 4, s = idx & 15;
            const __nv_bfloat16* gp = (m & 1) ? ql : qh;
            size_t go = rb + (size_t)r * QKV_N + (m >= 2 ? voff - seqbase * QKV_N
                                                         : koff - seqbase * QKV_N);
            cp16(base + (uint32_t)m * 17408u + (uint32_t)r * FRS + (uint32_t)s * 16u,
                 (const char*)(gp + go) + s * 16);
        }
        asm volatile("cp.async.commit_group;" ::: "memory");
    };

    load_kv(0, 0);
    asm volatile("cp.async.commit_group;" ::: "memory");

    float of[8][4];
    #pragma unroll
    for (int nf = 0; nf < 8; nf++)
        #pragma unroll
        for (int q = 0; q < 4; q++) of[nf][q] = 0.f;

    const uint32_t a_off = (uint32_t)(lane & 15) * FRS + (uint32_t)(lane >> 4) * 16u;
    const uint32_t b_off = (uint32_t)((lane & 7) + ((lane >> 4) << 3)) * FRS
                         + (uint32_t)((lane >> 3) & 1) * 16u;
    const uint32_t ap_off = (uint32_t)(lane & 15) * PRS + (uint32_t)(lane >> 4) * 16u;
    const uint32_t v_off = (uint32_t)((lane & 7) + ((lane >> 3) & 1) * 8) * FRS
                         + (uint32_t)(lane >> 4) * 16u;

    for (int kt = 0; kt <= qt; kt++) {
        int st = kt & 1;
        if (kt + 1 <= qt) {
            load_kv(kt + 1, st ^ 1);
            asm volatile("cp.async.wait_group 1;" ::: "memory");
        } else {
            asm volatile("cp.async.wait_group 0;" ::: "memory");
        }
        __syncthreads();

        const uint32_t kvbase = sb + FA_KV + (uint32_t)st * 69632u;

        float sc[4][4];
        #pragma unroll
        for (int nf = 0; nf < 4; nf++)
            #pragma unroll
            for (int q = 0; q < 4; q++) sc[nf][q] = 0.f;

        const uint32_t qh_b = sb + FA_QH + (uint32_t)(warp_m * 16) * FRS;
        const uint32_t ql_b = sb + FA_QL + (uint32_t)(warp_m * 16) * FRS;
        const uint32_t kh_b = kvbase + (uint32_t)(warp_n * 32) * FRS;
        const uint32_t kl_b = kvbase + 17408u + (uint32_t)(warp_n * 32) * FRS;

        #pragma unroll
        for (int ks = 0; ks < 8; ks++) {
            const uint32_t kb = (uint32_t)ks * 32u;
            uint32_t aH[4], aL[4], bH[4][2], bL[4][2];
            ldm4(aH, qh_b + a_off + kb);
            ldm4(aL, ql_b + a_off + kb);
            #pragma unroll
            for (int p = 0; p < 2; p++) {
                uint32_t r4[4];
                ldm4(r4, kh_b + b_off + (uint32_t)p * (16u * FRS) + kb);
                bH[2 * p][0] = r4[0]; bH[2 * p][1] = r4[1];
                bH[2 * p + 1][0] = r4[2]; bH[2 * p + 1][1] = r4[3];
                ldm4(r4, kl_b + b_off + (uint32_t)p * (16u * FRS) + kb);
                bL[2 * p][0] = r4[0]; bL[2 * p][1] = r4[1];
                bL[2 * p + 1][0] = r4[2]; bL[2 * p + 1][1] = r4[3];
            }
            #pragma unroll
            for (int nf = 0; nf < 4; nf++) mma_bf16(sc[nf], aH, bH[nf]);
            #pragma unroll
            for (int nf = 0; nf < 4; nf++) mma_bf16(sc[nf], aH, bL[nf]);
            #pragma unroll
            for (int nf = 0; nf < 4; nf++) mma_bf16(sc[nf], aL, bH[nf]);
        }

        {
            int r0 = warp_m * 16 + g;
            int qg0 = qt * 64 + r0;
            #pragma unroll
            for (int nf = 0; nf < 4; nf++) {
                int col = warp_n * 32 + nf * 8 + tg * 2;
                int kg  = kt * 64 + col;
                Ss[r0 * 65 + col]           = (kg     <= qg0)     ? sc[nf][0] * SCALE_F : -1e30f;
                Ss[r0 * 65 + col + 1]       = (kg + 1 <= qg0)     ? sc[nf][1] * SCALE_F : -1e30f;
                Ss[(r0 + 8) * 65 + col]     = (kg     <= qg0 + 8) ? sc[nf][2] * SCALE_F : -1e30f;
                Ss[(r0 + 8) * 65 + col + 1] = (kg + 1 <= qg0 + 8) ? sc[nf][3] * SCALE_F : -1e30f;
            }
        }
        __syncthreads();

        {
            int r  = tid >> 2;
            int q4 = (tid & 3) * 16;
            float mold = mrow[r];
            float mx = mold;
            #pragma unroll
            for (int cc = 0; cc < 16; cc++)
                mx = fmaxf(mx, Ss[r * 65 + q4 + cc]);
            mx = fmaxf(mx, __shfl_xor_sync(0xffffffffu, mx, 1));
            mx = fmaxf(mx, __shfl_xor_sync(0xffffffffu, mx, 2));
            float sum = 0.f;
            __nv_bfloat16* Ph = (__nv_bfloat16*)(smraw + FA_PH);
            __nv_bfloat16* Pl = (__nv_bfloat16*)(smraw + FA_PL);
            #pragma unroll
            for (int cc = 0; cc < 16; cc++) {
                float p = __expf(Ss[r * 65 + q4 + cc] - mx);
                sum += p;
                __nv_bfloat16 hi = __float2bfloat16(p);
                Ph[r * 72 + q4 + cc] = hi;
                Pl[r * 72 + q4 + cc] = __float2bfloat16(p - __bfloat162float(hi));
            }
            sum += __shfl_xor_sync(0xffffffffu, sum, 1);
            sum += __shfl_xor_sync(0xffffffffu, sum, 2);
            if ((tid & 3) == 0) {
                float al = __expf(mold - mx);
                lrow[r] = lrow[r] * al + sum;
                mrow[r] = mx;
                arow[r] = al;
            }
        }
        __syncthreads();

        {
            float al0 = arow[warp_m * 16 + g];
            float al1 = arow[warp_m * 16 + g + 8];
            #pragma unroll
            for (int nf = 0; nf < 8; nf++) {
                of[nf][0] *= al0; of[nf][1] *= al0;
                of[nf][2] *= al1; of[nf][3] *= al1;
            }
        }
        {
            const uint32_t ph_b = sb + FA_PH + (uint32_t)(warp_m * 16) * PRS;
            const uint32_t pl_b = sb + FA_PL + (uint32_t)(warp_m * 16) * PRS;
            const uint32_t vh_b = kvbase + 2u * 17408u + (uint32_t)(warp_n * 64) * 2u;
            const uint32_t vl_b = vh_b + 17408u;
            #pragma unroll
            for (int ks = 0; ks < 4; ks++) {
                uint32_t pH[4], pL[4], vH[8][2], vL[8][2];
                ldm4(pH, ph_b + ap_off + (uint32_t)ks * 32u);
                ldm4(pL, pl_b + ap_off + (uint32_t)ks * 32u);
                #pragma unroll
                for (int cl = 0; cl < 4; cl++) {
                    uint32_t r4[4];
                    ldm4t(r4, vh_b + v_off + (uint32_t)(ks * 16) * FRS
                              + (uint32_t)cl * 32u);
                    vH[2 * cl][0] = r4[0]; vH[2 * cl][1] = r4[1];
                    vH[2 * cl + 1][0] = r4[2]; vH[2 * cl + 1][1] = r4[3];
                    ldm4t(r4, vl_b + v_off + (uint32_t)(ks * 16) * FRS
                              + (uint32_t)cl * 32u);
                    vL[2 * cl][0] = r4[0]; vL[2 * cl][1] = r4[1];
                    vL[2 * cl + 1][0] = r4[2]; vL[2 * cl + 1][1] = r4[3];
                }
                #pragma unroll
                for (int nf = 0; nf < 8; nf++) mma_bf16(of[nf], pH, vH[nf]);
                #pragma unroll
                for (int nf = 0; nf < 8; nf++) mma_bf16(of[nf], pH, vL[nf]);
                #pragma unroll
                for (int nf = 0; nf < 8; nf++) mma_bf16(of[nf], pL, vH[nf]);
            }
        }
        __syncthreads();
    }

    {
        float inv0 = 1.0f / lrow[warp_m * 16 + g];
        float inv1 = 1.0f / lrow[warp_m * 16 + g + 8];
        size_t row0 = (seqbase + (size_t)qt * 64 + warp_m * 16 + g) * QSIZE
                    + (size_t)h * HDIM;
        size_t row1 = row0 + 8 * QSIZE;
        #pragma unroll
        for (int nf = 0; nf < 8; nf++) {
            int d = warp_n * 64 + nf * 8 + tg * 2;
            float v0 = of[nf][0] * inv0, v1 = of[nf][1] * inv0;
            float v2 = of[nf][2] * inv1, v3 = of[nf][3] * inv1;
            __nv_bfloat16 h0 = __float2bfloat16(v0), h1 = __float2bfloat16(v1);
            __nv_bfloat16 h2 = __float2bfloat16(v2), h3 = __float2bfloat16(v3);
            *(__nv_bfloat162*)&outH[row0 + d] = __nv_bfloat162(h0, h1);
            *(__nv_bfloat162*)&outH[row1 + d] = __nv_bfloat162(h2, h3);
            *(__nv_bfloat162*)&outL[row0 + d] = __nv_bfloat162(
                __float2bfloat16(v0 - __bfloat162float(h0)),
                __float2bfloat16(v1 - __bfloat162float(h1)));
            *(__nv_bfloat162*)&outL[row1 + d] = __nv_bfloat162(
                __float2bfloat16(v2 - __bfloat162float(h2)),
                __float2bfloat16(v3 - __bfloat162float(h3)));
        }
    }
}

// ---------------------------------------------------------------------------
// Launch
// ---------------------------------------------------------------------------
extern "C" void kernel_launch(void* const* d_in, const int* in_sizes, int n_in,
                              void* d_out, int out_size) {
    const void* positions = nullptr;
    const void* W_qkv_raw = nullptr;
    const void* c16[2]    = {nullptr, nullptr};
    int n16 = 0;
    for (int i = 0; i < n_in; i++) {
        if (in_sizes[i] == MROWS)               positions = d_in[i];
        else if (in_sizes[i] == HIDDEN * QKV_N) W_qkv_raw = d_in[i];
        else if (in_sizes[i] == MROWS * HIDDEN && n16 < 2)
            c16[n16++] = d_in[i];
    }
    const void* c0 = c16[0];
    const void* c1 = c16[1];

    __nv_bfloat16 *hidH, *hidL, *qkvH, *qkvL, *attnH, *attnL;
    __nv_bfloat16 *wqTH, *wqTL, *woTH, *woTL;
    cudaGetSymbolAddress((void**)&hidH,  g_hid_hi);
    cudaGetSymbolAddress((void**)&hidL,  g_hid_lo);
    cudaGetSymbolAddress((void**)&qkvH,  g_qkv_hi);
    cudaGetSymbolAddress((void**)&qkvL,  g_qkv_lo);
    cudaGetSymbolAddress((void**)&attnH, g_attn_hi);
    cudaGetSymbolAddress((void**)&attnL, g_attn_lo);
    cudaGetSymbolAddress((void**)&wqTH,  g_wqkvT_hi);
    cudaGetSymbolAddress((void**)&wqTL,  g_wqkvT_lo);
    cudaGetSymbolAddress((void**)&woTH,  g_woT_hi);
    cudaGetSymbolAddress((void**)&woTL,  g_woT_lo);

    // 0) Sniff dtype / hidden-vs-W_o / positions width
    sniff_kernel<<<1, 1>>>((const uint32_t*)W_qkv_raw, c0,
                           (const uint32_t*)positions);

    // 0b) Fused convert+split for hidden; transpose+convert+split for weights
    {
        size_t nh = (size_t)MROWS * HIDDEN;
        int thr = 256;
        csplit_kernel<<<(int)((nh / 4 + thr - 1) / thr), thr>>>(c0, c1,
                                                                hidH, hidL, nh);
        dim3 blk(32, 8);
        tsplit_raw<<<dim3(QKV_N / 32, HIDDEN / 32), blk>>>(
            W_qkv_raw, W_qkv_raw, wqTH, wqTL, HIDDEN, QKV_N, 0);
        tsplit_raw<<<dim3(HIDDEN / 32, QSIZE / 32), blk>>>(
            c1, c0, woTH, woTL, QSIZE, HIDDEN, 1);
    }

    cudaFuncSetAttribute(gemm_mma, cudaFuncAttributeMaxDynamicSharedMemorySize,
                         GM_SMEM);
    cudaFuncSetAttribute(flash_mma, cudaFuncAttributeMaxDynamicSharedMemorySize,
                         FA_TOTAL);

    // 1) QKV projection + fused RoPE + split output (mode 2)
    {
        dim3 grid(QKV_N / 128, MROWS / 128);
        gemm_mma<<<grid, 256, GM_SMEM>>>(hidH, hidL, wqTH, wqTL,
                                         nullptr, MROWS, QKV_N, HIDDEN, 2,
                                         (const int*)positions, qkvH, qkvL);
    }

    // 2) Flash attention on HMMA (writes split output directly)
    {
        dim3 grid(SEQ / 64, NHEADS, BATCH);
        flash_mma<<<grid, 256, FA_TOTAL>>>(qkvH, qkvL, attnH, attnL);
    }

    // 3) Output projection (mode 1: dtype-matched store)
    {
        dim3 grid(HIDDEN / 128, MROWS / 128);
        gemm_mma<<<grid, 256, GM_SMEM>>>(attnH, attnL, woTH, woTL,
                                         d_out, MROWS, HIDDEN, QSIZE, 1,
                                         nullptr, nullptr, nullptr);
    }
}